// round 14
// baseline (speedup 1.0000x reference)
#include <cuda_runtime.h>
#include <cuda_bf16.h>
#include <cstddef>
#include <cstdint>

#define NN 50000
#define NE 800000
#define C0 128   // in channels
#define C1 256   // hidden
#define C2 64    // latent

// ---------------- scratch (device globals; no allocation allowed) ----------------
__device__ int   g_deg[NN];
__device__ float g_dinv[NN];
__device__ int   g_is64;
__device__ int2  g_edge[NE];               // packed {src,dst}
__device__ int   g_rowstart[NN];
__device__ int   g_cursor[NN];
__device__ int   g_csr[NE];                // src indices grouped by dst
__device__ float g_aggx[(size_t)NN * C0];
__device__ float g_h1  [(size_t)NN * C1];
__device__ float g_t2  [(size_t)NN * C2];
__device__ float g_z   [(size_t)NN * C2];
__device__ float g_dd  [(size_t)NN * C1];

// ---------------- small kernels ----------------
// Zero degree array; thread 0 detects int64 vs int32 edge_index.
__global__ void k_prep(const void* ei) {
    int i = blockIdx.x * blockDim.x + threadIdx.x;
    if (i < NN) g_deg[i] = 0;
    if (i == 0) {
        const long long* p = (const long long*)ei;
        int ok = 1;
        for (int q = 0; q < 64; q++) {
            long long v = p[q];
            if (v < 0 || v >= NN) { ok = 0; break; }
        }
        g_is64 = ok;
    }
}

// decode indices once into int2 pairs + count in-degree; 4 edges per thread
__global__ void k_decode_count(const void* ei) {
    int t = blockIdx.x * blockDim.x + threadIdx.x;
    if (t >= NE / 4) return;
    int e = t * 4;
    int4 s4, d4;
    if (g_is64) {
        const longlong2* ps = (const longlong2*)((const long long*)ei + e);
        const longlong2* pd = (const longlong2*)((const long long*)ei + NE + e);
        longlong2 s01 = ps[0], s23 = ps[1];
        longlong2 d01 = pd[0], d23 = pd[1];
        s4 = make_int4((int)s01.x, (int)s01.y, (int)s23.x, (int)s23.y);
        d4 = make_int4((int)d01.x, (int)d01.y, (int)d23.x, (int)d23.y);
    } else {
        s4 = *(const int4*)((const int*)ei + e);
        d4 = *(const int4*)((const int*)ei + NE + e);
    }
    *(int4*)(g_edge + e)     = make_int4(s4.x, d4.x, s4.y, d4.y);
    *(int4*)(g_edge + e + 2) = make_int4(s4.z, d4.z, s4.w, d4.w);
    atomicAdd(&g_deg[d4.x], 1);
    atomicAdd(&g_deg[d4.y], 1);
    atomicAdd(&g_deg[d4.z], 1);
    atomicAdd(&g_deg[d4.w], 1);
}

// Single-block exclusive scan of degrees -> rowstart/cursor; also emits dinv.
__global__ void k_scan(void) {
    const int T = 1024;
    const int CH = (NN + T - 1) / T;   // 49
    __shared__ int part[T];
    int t = threadIdx.x;
    int base = t * CH;
    int sum = 0;
    for (int i = 0; i < CH; i++) {
        int idx = base + i;
        if (idx < NN) sum += g_deg[idx];
    }
    part[t] = sum;
    __syncthreads();
    // Hillis-Steele inclusive scan
    for (int off = 1; off < T; off <<= 1) {
        int v = (t >= off) ? part[t - off] : 0;
        __syncthreads();
        part[t] += v;
        __syncthreads();
    }
    int run = part[t] - sum;   // exclusive prefix for this chunk
    for (int i = 0; i < CH; i++) {
        int idx = base + i;
        if (idx >= NN) break;
        int dg = g_deg[idx];
        g_rowstart[idx] = run;
        g_cursor[idx]   = run;
        g_dinv[idx]     = rsqrtf((float)dg + 1.0f);   // +1 self loop
        run += dg;
    }
}

// Place src indices into CSR (grouped by dst). Order within a row follows
// atomic cursor order (fp-sum order varies, same as the atomic baseline).
__global__ void k_place() {
    int e = blockIdx.x * blockDim.x + threadIdx.x;
    if (e >= NE) return;
    int2 sd = g_edge[e];
    int pos = atomicAdd(&g_cursor[sd.y], 1);
    g_csr[pos] = sd.x;
}

// aggx[d] = dinv[d]^2 * x[d] + sum_{src in row(d)} dinv[src]*dinv[d]*x[src]
// one warp per dst row; 32 float4 lanes over 128 channels; no atomics.
__global__ void k_gather1(const float* __restrict__ x) {
    int gt = blockIdx.x * blockDim.x + threadIdx.x;
    int d = gt >> 5;
    int lane = gt & 31;
    if (d >= NN) return;
    float dvd = g_dinv[d];
    float4 acc = ((const float4*)x)[(size_t)d * 32 + lane];
    float s2 = dvd * dvd;
    acc.x *= s2; acc.y *= s2; acc.z *= s2; acc.w *= s2;
    int s = g_rowstart[d], len = g_deg[d];
    int src_n = (len > 0) ? __ldg(g_csr + s) : 0;
    for (int j = 0; j < len; j++) {
        int src = src_n;
        if (j + 1 < len) src_n = __ldg(g_csr + s + j + 1);   // prefetch
        float nm = dvd * g_dinv[src];
        float4 v = ((const float4*)x)[(size_t)src * 32 + lane];
        acc.x += nm * v.x; acc.y += nm * v.y;
        acc.z += nm * v.z; acc.w += nm * v.w;
    }
    ((float4*)g_aggx)[(size_t)d * 32 + lane] = acc;
}

// z[d] = dinv[d]^2 * t2[d] + b2 + sum dinv[s]*dinv[d]*t2[s]; 16 lanes per dst.
__global__ void k_gather2(const float* __restrict__ b2) {
    int gt = blockIdx.x * blockDim.x + threadIdx.x;
    int d = gt >> 4;
    int lane = gt & 15;
    if (d >= NN) return;
    float dvd = g_dinv[d];
    float4 acc = ((const float4*)g_t2)[(size_t)d * 16 + lane];
    float s2 = dvd * dvd;
    float4 bb = ((const float4*)b2)[lane];
    acc.x = acc.x * s2 + bb.x; acc.y = acc.y * s2 + bb.y;
    acc.z = acc.z * s2 + bb.z; acc.w = acc.w * s2 + bb.w;
    int s = g_rowstart[d], len = g_deg[d];
    int src_n = (len > 0) ? __ldg(g_csr + s) : 0;
    for (int j = 0; j < len; j++) {
        int src = src_n;
        if (j + 1 < len) src_n = __ldg(g_csr + s + j + 1);
        float nm = dvd * g_dinv[src];
        float4 v = ((const float4*)g_t2)[(size_t)src * 16 + lane];
        acc.x += nm * v.x; acc.y += nm * v.y;
        acc.z += nm * v.z; acc.w += nm * v.w;
    }
    ((float4*)g_z)[(size_t)d * 16 + lane] = acc;
}

// ---------------- GEMM: C[M,N] = A[M,K] @ B[K,N] (+bias) (+relu) ----------------
// Block tile 128 x BN, 256 threads, thread tile 8 x (BN/16), BK=16.
// Compile-time K; double-buffered smem; register prefetch; LDS.128 fragments;
// vectorized STG.128 epilogue.  (Measured-best fp32 design, 411.3us total.)
template <int BN, int K, int RELU, int BIAS>
__global__ __launch_bounds__(256)
void k_gemm(const float* __restrict__ A, const float* __restrict__ B,
            const float* __restrict__ bias, float* __restrict__ C,
            int M, int Nn) {
    constexpr int TN = BN / 16;
    constexpr int NB = BN / 64;
    constexpr int nT = K / 16;
    __shared__ float As[2][16][128];
    __shared__ float Bs[2][16][BN];
    int tid = threadIdx.x;
    int m0 = blockIdx.x * 128, n0 = blockIdx.y * BN;
    int ty = tid >> 4, tx = tid & 15;

    int af0 = tid * 2;
    int ar[2], akc[2];
#pragma unroll
    for (int q = 0; q < 2; q++) { ar[q] = (af0 + q) >> 2; akc[q] = ((af0 + q) & 3) << 2; }
    int br[NB], bnc[NB];
#pragma unroll
    for (int q = 0; q < NB; q++) {
        int f = tid + q * 256;
        br[q] = f / (BN / 4); bnc[q] = (f % (BN / 4)) * 4;
    }

    float acc[8][TN];
#pragma unroll
    for (int i = 0; i < 8; i++)
#pragma unroll
        for (int j = 0; j < TN; j++) acc[i][j] = 0.f;

    float4 ra[2], rb[NB];

#pragma unroll
    for (int q = 0; q < 2; q++)
        ra[q] = (m0 + ar[q] < M)
            ? *(const float4*)(A + (size_t)(m0 + ar[q]) * K + akc[q])
            : make_float4(0.f, 0.f, 0.f, 0.f);
#pragma unroll
    for (int q = 0; q < NB; q++)
        rb[q] = *(const float4*)(B + (size_t)br[q] * Nn + n0 + bnc[q]);
#pragma unroll
    for (int q = 0; q < 2; q++) {
        As[0][akc[q] + 0][ar[q]] = ra[q].x; As[0][akc[q] + 1][ar[q]] = ra[q].y;
        As[0][akc[q] + 2][ar[q]] = ra[q].z; As[0][akc[q] + 3][ar[q]] = ra[q].w;
    }
#pragma unroll
    for (int q = 0; q < NB; q++)
        *(float4*)&Bs[0][br[q]][bnc[q]] = rb[q];
    __syncthreads();

    int buf = 0;
#pragma unroll 1
    for (int t = 0; t < nT; t++) {
        if (t + 1 < nT) {
            int k0n = (t + 1) * 16;
#pragma unroll
            for (int q = 0; q < 2; q++)
                ra[q] = (m0 + ar[q] < M)
                    ? *(const float4*)(A + (size_t)(m0 + ar[q]) * K + k0n + akc[q])
                    : make_float4(0.f, 0.f, 0.f, 0.f);
#pragma unroll
            for (int q = 0; q < NB; q++)
                rb[q] = *(const float4*)(B + (size_t)(k0n + br[q]) * Nn + n0 + bnc[q]);
        }
#pragma unroll
        for (int k = 0; k < 16; k++) {
            float a[8], b[TN];
            *(float4*)&a[0] = *(const float4*)&As[buf][k][ty * 4];
            *(float4*)&a[4] = *(const float4*)&As[buf][k][ty * 4 + 64];
            *(float4*)&b[0] = *(const float4*)&Bs[buf][k][tx * 4];
            if (TN == 8)
                *(float4*)&b[4] = *(const float4*)&Bs[buf][k][tx * 4 + BN / 2];
#pragma unroll
            for (int i = 0; i < 8; i++)
#pragma unroll
                for (int j = 0; j < TN; j++)
                    acc[i][j] = fmaf(a[i], b[j], acc[i][j]);
        }
        if (t + 1 < nT) {
            int nb = buf ^ 1;
#pragma unroll
            for (int q = 0; q < 2; q++) {
                As[nb][akc[q] + 0][ar[q]] = ra[q].x; As[nb][akc[q] + 1][ar[q]] = ra[q].y;
                As[nb][akc[q] + 2][ar[q]] = ra[q].z; As[nb][akc[q] + 3][ar[q]] = ra[q].w;
            }
#pragma unroll
            for (int q = 0; q < NB; q++)
                *(float4*)&Bs[nb][br[q]][bnc[q]] = rb[q];
            __syncthreads();
            buf = nb;
        }
    }

    float4 bv[TN / 4];
#pragma unroll
    for (int g = 0; g < TN / 4; g++) {
        if (BIAS)
            bv[g] = *(const float4*)(bias + n0 + tx * 4 + g * (BN / 2));
        else
            bv[g] = make_float4(0.f, 0.f, 0.f, 0.f);
    }
#pragma unroll
    for (int i = 0; i < 8; i++) {
        int m = m0 + ty * 4 + (i >> 2) * 64 + (i & 3);
        if (m >= M) continue;
#pragma unroll
        for (int g = 0; g < TN / 4; g++) {
            float4 v;
            v.x = acc[i][g * 4 + 0] + bv[g].x;
            v.y = acc[i][g * 4 + 1] + bv[g].y;
            v.z = acc[i][g * 4 + 2] + bv[g].z;
            v.w = acc[i][g * 4 + 3] + bv[g].w;
            if (RELU) {
                v.x = fmaxf(v.x, 0.f); v.y = fmaxf(v.y, 0.f);
                v.z = fmaxf(v.z, 0.f); v.w = fmaxf(v.w, 0.f);
            }
            *(float4*)(C + (size_t)m * Nn + n0 + tx * 4 + g * (BN / 2)) = v;
        }
    }
}

// ---------------- launcher ----------------
extern "C" void kernel_launch(void* const* d_in, const int* in_sizes, int n_in,
                              void* d_out, int out_size) {
    const float* x   = (const float*)d_in[0];
    const void*  ei  = d_in[1];
    const float* W1  = (const float*)d_in[2];
    const float* b1  = (const float*)d_in[3];
    const float* W2  = (const float*)d_in[4];
    const float* b2  = (const float*)d_in[5];
    const float* Wd1 = (const float*)d_in[6];
    const float* bd1 = (const float*)d_in[7];
    const float* Wd2 = (const float*)d_in[8];
    const float* bd2 = (const float*)d_in[9];
    float* out = (float*)d_out;

    float *p_aggx, *p_h1, *p_t2, *p_z, *p_dd;
    cudaGetSymbolAddress((void**)&p_aggx, g_aggx);
    cudaGetSymbolAddress((void**)&p_h1,  g_h1);
    cudaGetSymbolAddress((void**)&p_t2,  g_t2);
    cudaGetSymbolAddress((void**)&p_z,   g_z);
    cudaGetSymbolAddress((void**)&p_dd,  g_dd);

    const int T = 256;
    // CSR build: degrees, scan (+dinv), placement
    k_prep<<<(NN + T - 1) / T, T>>>(ei);
    k_decode_count<<<(NE / 4 + T - 1) / T, T>>>(ei);
    k_scan<<<1, 1024>>>();
    k_place<<<(NE + T - 1) / T, T>>>();

    // layer 1: aggregate-then-transform (gather fuses self-loop)
    k_gather1<<<(NN * 32 + T - 1) / T, T>>>(x);
    k_gemm<128, C0, 1, 1><<<dim3((NN + 127) / 128, C1 / 128), T>>>(
        p_aggx, W1, b1, p_h1, NN, C1);

    // layer 2: transform-then-aggregate (gather fuses self-loop + bias)
    k_gemm<64, C1, 0, 0><<<dim3((NN + 127) / 128, 1), T>>>(
        p_h1, W2, nullptr, p_t2, NN, C2);
    k_gather2<<<(NN * 16 + T - 1) / T, T>>>(b2);

    // decoder MLP
    k_gemm<128, C2, 1, 1><<<dim3((NN + 127) / 128, C1 / 128), T>>>(
        p_z, Wd1, bd1, p_dd, NN, C1);
    k_gemm<128, C1, 0, 1><<<dim3((NN + 127) / 128, C0 / 128), T>>>(
        p_dd, Wd2, bd2, out, NN, C0);
}